// round 1
// baseline (speedup 1.0000x reference)
#include <cuda_runtime.h>
#include <cstdint>

typedef unsigned long long u64;

#define DEVINL __device__ __forceinline__

DEVINL u64 pack2(float lo, float hi) {
    u64 d;
    asm("mov.b64 %0, {%1, %2};" : "=l"(d) : "f"(lo), "f"(hi));
    return d;
}
DEVINL void unpack2(u64 v, float& lo, float& hi) {
    asm("mov.b64 {%0, %1}, %2;" : "=f"(lo), "=f"(hi) : "l"(v));
}
DEVINL u64 ffma2(u64 a, u64 b, u64 c) {
    u64 d;
    asm("fma.rn.f32x2 %0, %1, %2, %3;" : "=l"(d) : "l"(a), "l"(b), "l"(c));
    return d;
}

// smooth_leaky_relu(x) = 0.6x + 0.4x*tanh(x/2)   (alpha=0.2)
DEVINL float act_fn(float v) {
    float t;
    asm("tanh.approx.f32 %0, %1;" : "=f"(t) : "f"(0.5f * v));
    return v * (0.6f + 0.4f * t);
}

// ---------------- constants ----------------
static constexpr int ROWLEN  = 592;
static constexpr int THREADS = 256;
static constexpr int RPB     = 64;     // rows per block (all segments)

// transposed-weight scratch: Wt[k][o] per segment, packed back-to-back
__device__ float g_wt[16384 + 4096 + 1024 + 256];

__global__ void prep_kernel(const float* __restrict__ w0, const float* __restrict__ w1,
                            const float* __restrict__ w2, const float* __restrict__ w3) {
    int idx = blockIdx.x * 256 + threadIdx.x;
    if (idx < 16384) {
        int k = idx >> 7, o = idx & 127;
        g_wt[idx] = w0[o * 128 + k];
    } else if (idx < 20480) {
        int t = idx - 16384; int k = t >> 6, o = t & 63;
        g_wt[idx] = w1[o * 64 + k];
    } else if (idx < 21504) {
        int t = idx - 20480; int k = t >> 5, o = t & 31;
        g_wt[idx] = w2[o * 32 + k];
    } else if (idx < 21760) {
        int t = idx - 21504; int k = t >> 4, o = t & 15;
        g_wt[idx] = w3[o * 16 + k];
    }
}

// SCHEME 0: accumulators packed over output pairs (o,o+1)  -> W pairs loaded as u64, X duplicated via mov
// SCHEME 1: accumulators packed over column pairs (c,c+1)  -> X pairs loaded as u64, W duplicated via mov
template<int MUL, int D, int DPAD, int IN_OFF, int WOFF, int SCHEME, bool ACT>
__global__ __launch_bounds__(THREADS)
void seg_kernel(const float* __restrict__ x, const float* __restrict__ bias,
                float* __restrict__ out, int N) {
    constexpr int K      = MUL;
    constexpr int CBLK   = RPB * DPAD;
    constexpr int TC     = CBLK / 32;
    constexpr int TO     = MUL / 8;
    constexpr int SEGLEN = MUL * D;
    constexpr int SEGF4  = SEGLEN / 4;
    constexpr int PX     = CBLK + (SCHEME ? 2 : 1);
    constexpr int PO     = MUL + 1;
    constexpr int WS_SZ  = K * MUL;

    extern __shared__ float smem[];
    float* Ws = smem;
    float* Xs = smem + WS_SZ;   // aliased with Os after GEMM
    float* Os = Xs;

    const int tid  = threadIdx.x;
    const int lane = tid & 31;
    const int warp = tid >> 5;
    const int r0   = blockIdx.x * RPB;
    const int nrows = min(RPB, N - r0);
    const int nwork = nrows * SEGF4;

    // --- load transposed weights (coalesced, conflict-free) ---
    #pragma unroll 1
    for (int i = tid; i < WS_SZ / 4; i += THREADS)
        ((float4*)Ws)[i] = ((const float4*)(g_wt + WOFF))[i];

    // --- load X tile, transpose into Xs[k][c],  c = r*DPAD + dd ---
    #pragma unroll 1
    for (int i = tid; i < nwork; i += THREADS) {
        int r = i / SEGF4;
        int q = i - r * SEGF4;
        float4 v = *(const float4*)(x + (size_t)(r0 + r) * ROWLEN + IN_OFF + 4 * q);
        int j = 4 * q;
        float vv[4] = {v.x, v.y, v.z, v.w};
        #pragma unroll
        for (int e = 0; e < 4; e++) {
            int k  = (j + e) / D;
            int dd = (j + e) - k * D;
            Xs[k * PX + r * DPAD + dd] = vv[e];
        }
    }
    __syncthreads();

    const int ob = warp * TO;

    if (SCHEME == 0) {
        // ---- o-pair scheme ----
        u64 acc[TC][TO / 2];
        #pragma unroll
        for (int p = 0; p < TO / 2; p++) {
            u64 bp = pack2(__ldg(bias + ob + 2 * p), __ldg(bias + ob + 2 * p + 1));
            #pragma unroll
            for (int i = 0; i < TC; i++) acc[i][p] = bp;
        }
        #pragma unroll 4
        for (int k = 0; k < K; k++) {
            u64 xd[TC];
            #pragma unroll
            for (int i = 0; i < TC; i++) {
                float xv = Xs[k * PX + lane + 32 * i];
                xd[i] = pack2(xv, xv);
            }
            const u64* wrow = (const u64*)(Ws + k * MUL + ob);
            u64 wp[TO / 2];
            #pragma unroll
            for (int p = 0; p < TO / 2; p++) wp[p] = wrow[p];
            #pragma unroll
            for (int i = 0; i < TC; i++)
                #pragma unroll
                for (int p = 0; p < TO / 2; p++)
                    acc[i][p] = ffma2(wp[p], xd[i], acc[i][p]);
        }
        __syncthreads();
        #pragma unroll
        for (int i = 0; i < TC; i++) {
            int c = lane + 32 * i;
            #pragma unroll
            for (int p = 0; p < TO / 2; p++) {
                float lo, hi; unpack2(acc[i][p], lo, hi);
                Os[c * PO + ob + 2 * p]     = lo;
                Os[c * PO + ob + 2 * p + 1] = hi;
            }
        }
    } else {
        // ---- c-pair scheme ----
        u64 acc[TC / 2][TO];
        #pragma unroll
        for (int t = 0; t < TO; t++) {
            float b = __ldg(bias + ob + t);
            u64 bp = pack2(b, b);
            #pragma unroll
            for (int i = 0; i < TC / 2; i++) acc[i][t] = bp;
        }
        #pragma unroll 4
        for (int k = 0; k < K; k++) {
            u64 xp[TC / 2];
            #pragma unroll
            for (int i = 0; i < TC / 2; i++)
                xp[i] = *(const u64*)(Xs + k * PX + 2 * lane + 64 * i);
            u64 wd[TO];
            #pragma unroll
            for (int t = 0; t < TO; t++) {
                float w = Ws[k * MUL + ob + t];
                wd[t] = pack2(w, w);
            }
            #pragma unroll
            for (int i = 0; i < TC / 2; i++)
                #pragma unroll
                for (int t = 0; t < TO; t++)
                    acc[i][t] = ffma2(xp[i], wd[t], acc[i][t]);
        }
        __syncthreads();
        #pragma unroll
        for (int i = 0; i < TC / 2; i++) {
            int c = 2 * lane + 64 * i;
            #pragma unroll
            for (int t = 0; t < TO; t++) {
                float lo, hi; unpack2(acc[i][t], lo, hi);
                Os[c * PO + ob + t]       = lo;
                Os[(c + 1) * PO + ob + t] = hi;
            }
        }
    }
    __syncthreads();

    // --- store: read staged Os, coalesced float4 to gmem ---
    #pragma unroll 1
    for (int i = tid; i < nwork; i += THREADS) {
        int r = i / SEGF4;
        int q = i - r * SEGF4;
        int j = 4 * q;
        float vv[4];
        #pragma unroll
        for (int e = 0; e < 4; e++) {
            int o  = (j + e) / D;
            int dd = (j + e) - o * D;
            float val = Os[(r * DPAD + dd) * PO + o];
            if (ACT) val = act_fn(val);
            vv[e] = val;
        }
        float4 v; v.x = vv[0]; v.y = vv[1]; v.z = vv[2]; v.w = vv[3];
        *(float4*)(out + (size_t)(r0 + r) * ROWLEN + IN_OFF + 4 * q) = v;
    }
}

// segment configs:            MUL  D DPAD IN_OFF  WOFF  SCHEME ACT
using Seg0 = void(const float*, const float*, float*, int);
static constexpr int S0_SMEM = (16384 + 128 * 65) * 4;            // Ws + max(Xs 128x65, Os 64x129)
static constexpr int S1_SMEM = (4096  + 192 * 65) * 4;            // Os 192x65 > Xs 64x193
static constexpr int S2_SMEM = (1024  + 320 * 33) * 4;            // Os 320x33 > Xs 32x322
static constexpr int S3_SMEM = (256   + 512 * 17) * 4;            // Os 512x17 > Xs 16x514

extern "C" void kernel_launch(void* const* d_in, const int* in_sizes, int n_in,
                              void* d_out, int out_size) {
    const float* x  = (const float*)d_in[0];
    const float* w0 = (const float*)d_in[1];
    const float* w1 = (const float*)d_in[2];
    const float* w2 = (const float*)d_in[3];
    const float* w3 = (const float*)d_in[4];
    const float* b0 = (const float*)d_in[5];
    const float* b1 = (const float*)d_in[6];
    const float* b2 = (const float*)d_in[7];
    const float* b3 = (const float*)d_in[8];
    float* out = (float*)d_out;
    const int N = in_sizes[0] / ROWLEN;

    auto k0 = seg_kernel<128, 1, 1,   0,     0, 0, true >;
    auto k1 = seg_kernel< 64, 3, 3, 128, 16384, 0, false>;
    auto k2 = seg_kernel< 32, 5, 5, 320, 20480, 1, false>;
    auto k3 = seg_kernel< 16, 7, 8, 480, 21504, 1, false>;

    cudaFuncSetAttribute(k0, cudaFuncAttributeMaxDynamicSharedMemorySize, S0_SMEM);
    cudaFuncSetAttribute(k1, cudaFuncAttributeMaxDynamicSharedMemorySize, S1_SMEM);
    cudaFuncSetAttribute(k2, cudaFuncAttributeMaxDynamicSharedMemorySize, S2_SMEM);
    cudaFuncSetAttribute(k3, cudaFuncAttributeMaxDynamicSharedMemorySize, S3_SMEM);

    prep_kernel<<<85, 256>>>(w0, w1, w2, w3);

    const int grid = (N + RPB - 1) / RPB;   // 1563 for N=100000
    k0<<<grid, THREADS, S0_SMEM>>>(x, b0, out, N);
    k1<<<grid, THREADS, S1_SMEM>>>(x, b1, out, N);
    k2<<<grid, THREADS, S2_SMEM>>>(x, b2, out, N);
    k3<<<grid, THREADS, S3_SMEM>>>(x, b3, out, N);
}